// round 3
// baseline (speedup 1.0000x reference)
#include <cuda_runtime.h>
#include <math.h>

#define NB   2048
#define NC   9605
#define NL   20
#define TPB  256

#define ALPHA   0.5f
#define ALPHA1  0.05f
#define ALPHA2  2.0f
#define ALPHA3  10.0f

__device__ signed char g_class_group[NC];
__device__ float g_row_loss[NB];
__device__ int g_mask_is_u8;   // 1 if group_mask buffer is 1 byte/elem, 0 if int32

// ---------------------------------------------------------------------------
// Dtype detection for the bool mask. Reading the first NL*NC bytes is safe
// under either layout (int32 buffer is 4x larger). In an int32 0/1 buffer,
// nonzero bytes appear only at offsets % 4 == 0; in a uint8 bool buffer the
// ~1000 trues hit misaligned offsets almost surely.
// ---------------------------------------------------------------------------
__global__ void init_flag_kernel() { g_mask_is_u8 = 0; }

__global__ void detect_mask_kernel(const unsigned char* __restrict__ mask) {
    int i = blockIdx.x * blockDim.x + threadIdx.x;
    if (i >= NL * NC) return;
    if ((i & 3) != 0 && mask[i] != 0) atomicOr(&g_mask_is_u8, 1);
}

// ---------------------------------------------------------------------------
// Build per-class group id from the [L, C] mask (disjoint groups).
// ---------------------------------------------------------------------------
__global__ void build_class_group_kernel(const void* __restrict__ maskv) {
    int c = blockIdx.x * blockDim.x + threadIdx.x;
    if (c >= NC) return;
    const int u8 = g_mask_is_u8;
    signed char g = -1;
    if (u8) {
        const unsigned char* m = (const unsigned char*)maskv;
        #pragma unroll
        for (int l = 0; l < NL; l++)
            if (m[(size_t)l * NC + c]) { g = (signed char)l; break; }
    } else {
        const int* m = (const int*)maskv;
        #pragma unroll
        for (int l = 0; l < NL; l++)
            if (m[(size_t)l * NC + c] != 0) { g = (signed char)l; break; }
    }
    g_class_group[c] = g;
}

// Order-preserving float <-> uint encoding for atomicMax on shared memory.
__device__ __forceinline__ unsigned int fenc(float f) {
    unsigned int u = __float_as_uint(f);
    return (u & 0x80000000u) ? ~u : (u | 0x80000000u);
}
__device__ __forceinline__ float fdec(unsigned int u) {
    return (u & 0x80000000u) ? __uint_as_float(u ^ 0x80000000u)
                             : __uint_as_float(~u);
}

__device__ __forceinline__ float sigmoidf_(float v) {
    return 1.0f / (1.0f + expf(-v));
}

// our_rank_loss(x1, x2, margin=ALPHA1)
__device__ __forceinline__ float rank_loss(float x1, float x2) {
    float d = x2 - x1 + ALPHA1;
    float s = 1.0f / (1.0f + expf(-ALPHA3 * d));
    return (d > 0.0f) ? (ALPHA2 * s) : s;
}

// ---------------------------------------------------------------------------
// One block per row. 256 threads stride over C classes.
// ---------------------------------------------------------------------------
__global__ __launch_bounds__(TPB)
void row_loss_kernel(const float* __restrict__ x,
                     const int*   __restrict__ y,
                     const int*   __restrict__ yneg) {
    const int b   = blockIdx.x;
    const int tid = threadIdx.x;

    __shared__ unsigned int gmax_sh[NL];
    __shared__ int act_sh[NL];
    __shared__ int actn_sh[NL];
    __shared__ float tops[TPB * 11];

    if (tid < NL) {
        gmax_sh[tid] = fenc(-3.0e38f);
        act_sh[tid]  = 0;
        actn_sh[tid] = 0;
    }
    __syncthreads();

    const float* xr  = x    + (size_t)b * NC;
    const int*   yr  = y    + (size_t)b * NC;
    const int*   ynr = yneg + (size_t)b * NC;

    // Per-thread top-11 in registers (descending), constant-index unrolled
    // insertion keeps the array in registers.
    float t[11];
    #pragma unroll
    for (int i = 0; i < 11; i++) t[i] = -3.0e38f;

    for (int c = tid; c < NC; c += TPB) {
        float v = __ldg(xr + c);

        if (v > t[10]) {
            t[10] = v;
            #pragma unroll
            for (int j = 10; j > 0; j--) {
                float a = t[j - 1], bb = t[j];
                t[j - 1] = fmaxf(a, bb);
                t[j]     = fminf(a, bb);
            }
        }

        int gid = (int)g_class_group[c];
        if (gid >= 0) {
            atomicMax(&gmax_sh[gid], fenc(v));
            if (__ldg(yr + c) != 0)  act_sh[gid]  = 1;  // idempotent store
            if (__ldg(ynr + c) != 0) actn_sh[gid] = 1;
        }
    }

    #pragma unroll
    for (int i = 0; i < 11; i++) tops[tid * 11 + i] = t[i];
    __syncthreads();

    // Tree-merge sorted 11-lists down to one global top-11.
    for (int s = TPB / 2; s >= 1; s >>= 1) {
        if (tid < s) {
            float* A  = &tops[tid * 11];
            float* Bp = &tops[(tid + s) * 11];
            float out[11];
            int i = 0, j = 0;
            #pragma unroll
            for (int k = 0; k < 11; k++) {
                float av = A[i], bv = Bp[j];
                if (av >= bv) { out[k] = av; i++; }
                else          { out[k] = bv; j++; }
            }
            #pragma unroll
            for (int k = 0; k < 11; k++) A[k] = out[k];
        }
        __syncthreads();
    }

    if (tid == 0) {
        float x11   = tops[10];                  // 11th largest raw score
        float thres = sigmoidf_(fmaxf(x11, 0.0f));

        float s_l[NL];
        int   g = -1;
        float union_max = 0.0f;
        #pragma unroll
        for (int l = 0; l < NL; l++) {
            s_l[l] = sigmoidf_(fdec(gmax_sh[l]));
            union_max = fmaxf(union_max, s_l[l]);
            if (g < 0 && act_sh[l]) g = l;
        }
        bool has_gt = (g >= 0);

        float incorrect_neg = 0.0f;
        #pragma unroll
        for (int l = 0; l < NL; l++)
            if (actn_sh[l]) incorrect_neg = fmaxf(incorrect_neg, s_l[l]);

        float loss;
        if (!has_gt) {
            loss = (1.0f - ALPHA) * rank_loss(thres, union_max)
                 + ALPHA          * rank_loss(thres, incorrect_neg);
        } else {
            float gt_max = s_l[g];
            float incorrect_max = 0.0f;
            #pragma unroll
            for (int l = 0; l < NL; l++)
                if (l != g) incorrect_max = fmaxf(incorrect_max, s_l[l]);

            loss = rank_loss(gt_max, thres);
            if (incorrect_max > 0.0f)
                loss += (1.0f - ALPHA) * rank_loss(thres, incorrect_max);
            if (incorrect_neg > 0.0f)
                loss += ALPHA * rank_loss(thres, incorrect_neg);
            else
                loss += ALPHA * rank_loss(thres, incorrect_max);
        }
        g_row_loss[b] = loss;
    }
}

// ---------------------------------------------------------------------------
// Deterministic fixed-order tree reduction of the 2048 row losses.
// ---------------------------------------------------------------------------
__global__ void reduce_kernel(float* __restrict__ out) {
    __shared__ float s[1024];
    int tid = threadIdx.x;
    s[tid] = g_row_loss[tid] + g_row_loss[tid + 1024];
    __syncthreads();
    for (int st = 512; st >= 1; st >>= 1) {
        if (tid < st) s[tid] += s[tid + st];
        __syncthreads();
    }
    if (tid == 0) out[0] = s[0];
}

extern "C" void kernel_launch(void* const* d_in, const int* in_sizes, int n_in,
                              void* d_out, int out_size) {
    const float* x    = (const float*)d_in[0];
    const int*   y    = (const int*)d_in[1];
    const int*   yneg = (const int*)d_in[2];
    const void*  gmask = d_in[3];

    init_flag_kernel<<<1, 1>>>();
    detect_mask_kernel<<<(NL * NC + 255) / 256, 256>>>((const unsigned char*)gmask);
    build_class_group_kernel<<<(NC + 255) / 256, 256>>>(gmask);
    row_loss_kernel<<<NB, TPB>>>(x, y, yneg);
    reduce_kernel<<<1, 1024>>>((float*)d_out);
}

// round 6
// speedup vs baseline: 1.6049x; 1.6049x over previous
#include <cuda_runtime.h>
#include <math.h>

#define NB   2048
#define NC   9605
#define NL   20
#define TPB  256
#define MAXWL 2048   // capacity for whitelist list (actual = L*G = 1000)

#define ALPHA   0.5f
#define ALPHA1  0.05f
#define ALPHA2  2.0f
#define ALPHA3  10.0f

__device__ float g_row_loss[NB];
__device__ int   g_mask_is_u8;
__device__ int   g_wl_cnt;
__device__ int   g_wl_packed[MAXWL];   // (class_idx << 5) | group_id

// ---------------------------------------------------------------------------
// Prelude: detect mask dtype, build compact whitelist list.
// ---------------------------------------------------------------------------
__global__ void init_kernel() { g_mask_is_u8 = 0; g_wl_cnt = 0; }

__global__ void detect_mask_kernel(const unsigned char* __restrict__ mask) {
    int i = blockIdx.x * blockDim.x + threadIdx.x;
    if (i >= NL * NC) return;
    // int32 0/1 buffer: nonzero bytes only at offset%4==0. uint8 bool buffer:
    // trues hit misaligned offsets almost surely.
    if ((i & 3) != 0 && mask[i] != 0) atomicOr(&g_mask_is_u8, 1);
}

__global__ void build_wl_kernel(const void* __restrict__ maskv) {
    int c = blockIdx.x * blockDim.x + threadIdx.x;
    if (c >= NC) return;
    const int u8 = g_mask_is_u8;
    int g = -1;
    if (u8) {
        const unsigned char* m = (const unsigned char*)maskv;
        #pragma unroll
        for (int l = 0; l < NL; l++)
            if (m[(size_t)l * NC + c]) { g = l; break; }
    } else {
        const int* m = (const int*)maskv;
        #pragma unroll
        for (int l = 0; l < NL; l++)
            if (m[(size_t)l * NC + c] != 0) { g = l; break; }
    }
    if (g >= 0) {
        int pos = atomicAdd(&g_wl_cnt, 1);
        if (pos < MAXWL) g_wl_packed[pos] = (c << 5) | g;
    }
}

// ---------------------------------------------------------------------------
// Helpers
// ---------------------------------------------------------------------------
__device__ __forceinline__ unsigned int fenc(float f) {
    unsigned int u = __float_as_uint(f);
    return (u & 0x80000000u) ? ~u : (u | 0x80000000u);
}
__device__ __forceinline__ float fdec(unsigned int u) {
    return (u & 0x80000000u) ? __uint_as_float(u ^ 0x80000000u)
                             : __uint_as_float(~u);
}
__device__ __forceinline__ float sigmoidf_(float v) {
    return 1.0f / (1.0f + expf(-v));
}
__device__ __forceinline__ float rank_loss(float x1, float x2) {
    float d = x2 - x1 + ALPHA1;
    float s = 1.0f / (1.0f + expf(-ALPHA3 * d));
    return (d > 0.0f) ? (ALPHA2 * s) : s;
}

// Insert one value into a descending register-resident top-11.
#define TOP11_INSERT(t, v)                                   \
    if ((v) > t[10]) {                                       \
        t[10] = (v);                                         \
        _Pragma("unroll")                                    \
        for (int _j = 10; _j > 0; _j--) {                    \
            float _a = t[_j - 1], _b = t[_j];                \
            t[_j - 1] = fmaxf(_a, _b);                       \
            t[_j]     = fminf(_a, _b);                       \
        }                                                    \
    }

// ---------------------------------------------------------------------------
// One block per row.
// ---------------------------------------------------------------------------
__global__ __launch_bounds__(TPB)
void row_loss_kernel(const float* __restrict__ x,
                     const int*   __restrict__ y,
                     const int*   __restrict__ yneg) {
    const int b   = blockIdx.x;
    const int tid = threadIdx.x;

    __shared__ unsigned int gmax_sh[NL];
    __shared__ int act_sh[NL];
    __shared__ int actn_sh[NL];
    __shared__ float tops[TPB * 11];

    if (tid < NL) {
        gmax_sh[tid] = fenc(-3.0e38f);
        act_sh[tid]  = 0;
        actn_sh[tid] = 0;
    }
    __syncthreads();

    const float* xr  = x    + (size_t)b * NC;
    const int*   yr  = y    + (size_t)b * NC;
    const int*   ynr = yneg + (size_t)b * NC;

    float t[11];
    #pragma unroll
    for (int i = 0; i < 11; i++) t[i] = -3.0e38f;

    // ---- Dense phase: float4-vectorized top-11 scan --------------------
    // Row base alignment varies (9605*4 = 38420 bytes, mod 16 = 4): peel to
    // the next 16B boundary, then vector body, then scalar tail.
    const int p    = (int)(((16u - ((unsigned)(size_t)xr & 15u)) & 15u) >> 2);
    const int nvec = (NC - p) >> 2;
    const int tail = p + (nvec << 2);

    for (int c = tid; c < p; c += TPB) {           // at most 3 elems
        float v = __ldg(xr + c);
        TOP11_INSERT(t, v);
    }
    const float4* v4 = (const float4*)(xr + p);
    for (int i = tid; i < nvec; i += TPB) {
        float4 q = __ldg(v4 + i);
        float m = fmaxf(fmaxf(q.x, q.y), fmaxf(q.z, q.w));
        if (m > t[10]) {                           // rare after warm-up
            TOP11_INSERT(t, q.x);
            TOP11_INSERT(t, q.y);
            TOP11_INSERT(t, q.z);
            TOP11_INSERT(t, q.w);
        }
    }
    for (int c = tail + tid; c < NC; c += TPB) {   // at most 3 elems
        float v = __ldg(xr + c);
        TOP11_INSERT(t, v);
    }

    // ---- Whitelist phase: 1000 compact gathers --------------------------
    const int cnt = g_wl_cnt;
    for (int i = tid; i < cnt; i += TPB) {
        int pk  = g_wl_packed[i];
        int c   = pk >> 5;
        int gid = pk & 31;
        float v = __ldg(xr + c);                   // L1-hot from dense phase
        atomicMax(&gmax_sh[gid], fenc(v));
        if (__ldg(yr + c) != 0)  act_sh[gid]  = 1; // idempotent
        if (__ldg(ynr + c) != 0) actn_sh[gid] = 1;
    }

    #pragma unroll
    for (int i = 0; i < 11; i++) tops[tid * 11 + i] = t[i];
    __syncthreads();

    // ---- Tree-merge sorted 11-lists -------------------------------------
    for (int s = TPB / 2; s >= 1; s >>= 1) {
        if (tid < s) {
            float* A  = &tops[tid * 11];
            float* Bp = &tops[(tid + s) * 11];
            float out[11];
            int i = 0, j = 0;
            #pragma unroll
            for (int k = 0; k < 11; k++) {
                float av = A[i], bv = Bp[j];
                if (av >= bv) { out[k] = av; i++; }
                else          { out[k] = bv; j++; }
            }
            #pragma unroll
            for (int k = 0; k < 11; k++) A[k] = out[k];
        }
        __syncthreads();
    }

    // ---- Scalar epilogue -------------------------------------------------
    if (tid == 0) {
        float x11   = tops[10];
        float thres = sigmoidf_(fmaxf(x11, 0.0f));

        float s_l[NL];
        int   g = -1;
        float union_max = 0.0f;
        #pragma unroll
        for (int l = 0; l < NL; l++) {
            s_l[l] = sigmoidf_(fdec(gmax_sh[l]));
            union_max = fmaxf(union_max, s_l[l]);
            if (g < 0 && act_sh[l]) g = l;
        }
        bool has_gt = (g >= 0);

        float incorrect_neg = 0.0f;
        #pragma unroll
        for (int l = 0; l < NL; l++)
            if (actn_sh[l]) incorrect_neg = fmaxf(incorrect_neg, s_l[l]);

        float loss;
        if (!has_gt) {
            loss = (1.0f - ALPHA) * rank_loss(thres, union_max)
                 + ALPHA          * rank_loss(thres, incorrect_neg);
        } else {
            float gt_max = s_l[g];
            float incorrect_max = 0.0f;
            #pragma unroll
            for (int l = 0; l < NL; l++)
                if (l != g) incorrect_max = fmaxf(incorrect_max, s_l[l]);

            loss = rank_loss(gt_max, thres);
            if (incorrect_max > 0.0f)
                loss += (1.0f - ALPHA) * rank_loss(thres, incorrect_max);
            if (incorrect_neg > 0.0f)
                loss += ALPHA * rank_loss(thres, incorrect_neg);
            else
                loss += ALPHA * rank_loss(thres, incorrect_max);
        }
        g_row_loss[b] = loss;
    }
}

// ---------------------------------------------------------------------------
// Deterministic fixed-order tree reduction of the 2048 row losses.
// ---------------------------------------------------------------------------
__global__ void reduce_kernel(float* __restrict__ out) {
    __shared__ float s[1024];
    int tid = threadIdx.x;
    s[tid] = g_row_loss[tid] + g_row_loss[tid + 1024];
    __syncthreads();
    for (int st = 512; st >= 1; st >>= 1) {
        if (tid < st) s[tid] += s[tid + st];
        __syncthreads();
    }
    if (tid == 0) out[0] = s[0];
}

extern "C" void kernel_launch(void* const* d_in, const int* in_sizes, int n_in,
                              void* d_out, int out_size) {
    const float* x    = (const float*)d_in[0];
    const int*   y    = (const int*)d_in[1];
    const int*   yneg = (const int*)d_in[2];
    const void*  gmask = d_in[3];

    init_kernel<<<1, 1>>>();
    detect_mask_kernel<<<(NL * NC + 255) / 256, 256>>>((const unsigned char*)gmask);
    build_wl_kernel<<<(NC + 255) / 256, 256>>>(gmask);
    row_loss_kernel<<<NB, TPB>>>(x, y, yneg);
    reduce_kernel<<<1, 1024>>>((float*)d_out);
}